// round 6
// baseline (speedup 1.0000x reference)
#include <cuda_runtime.h>
#include <math.h>

#define NS  1024
#define XD  128
#define HID 256

typedef unsigned long long ull;

// scratch (allocation-free rule: __device__ globals)
__device__ float g_pxT[HID * NS];   // [k][j] : px transposed
__device__ float g_pybT[HID * NS];  // [k][i] : (y@W1y + b1) transposed
__device__ float g_diag[NS];        // T1[i,i]
__device__ float g_e[NS];           // exp(lse_i - ln N)

// ---------------------------------------------------------------------------
// packed f32x2 helpers (sm_100+)
// ---------------------------------------------------------------------------
__device__ __forceinline__ ull dup2(float x) {
    ull r;
    asm("mov.b64 %0, {%1, %1};" : "=l"(r) : "f"(x));
    return r;
}

// acc2 += max(a2 + p2, 0) * w2   (elementwise on both packed lanes)
__device__ __forceinline__ void relu_fma2(ull& acc, ull a2, ull p2, ull w2) {
    asm("{\n\t"
        ".reg .b64 v;\n\t"
        ".reg .f32 lo, hi;\n\t"
        "add.rn.f32x2 v, %1, %2;\n\t"
        "mov.b64 {lo, hi}, v;\n\t"
        "max.f32 lo, lo, 0f00000000;\n\t"
        "max.f32 hi, hi, 0f00000000;\n\t"
        "mov.b64 v, {lo, hi};\n\t"
        "fma.rn.f32x2 %0, v, %3, %0;\n\t"
        "}"
        : "+l"(acc) : "l"(a2), "l"(p2), "l"(w2));
}

// ---------------------------------------------------------------------------
// GEMM: C_T[h][n] = sum_d A[n][d] * W1[z*128 + d][h]   (+ b1[h] when z==1)
// block tile 64h x 64n, 256 threads, thread tile 4h x 4n, smem-tiled,
// LDS.128 reads. (unchanged from R5: measured 10.3us)
// ---------------------------------------------------------------------------
__global__ __launch_bounds__(256) void gemm_kernel(
    const float* __restrict__ X, const float* __restrict__ Y,
    const float* __restrict__ W1, const float* __restrict__ b1)
{
    const int z  = blockIdx.z;
    const float* A = z ? Y : X;
    float* C = z ? g_pybT : g_pxT;
    const int h0 = blockIdx.y * 64;
    const int n0 = blockIdx.x * 64;
    const int t  = threadIdx.x;
    const int tx = t & 15;   // n quad index
    const int ty = t >> 4;   // h quad index

    __shared__ float xs[64][68];  // [d][n] transposed, pad 68
    __shared__ float ws[64][64];  // [d][h]

    float acc[4][4];
#pragma unroll
    for (int i = 0; i < 4; i++)
#pragma unroll
        for (int j = 0; j < 4; j++) acc[i][j] = 0.f;

    for (int k0 = 0; k0 < XD; k0 += 64) {
        __syncthreads();
#pragma unroll
        for (int r = 0; r < 4; r++) {
            int f = t + 256 * r;          // 1024 float4s
            int n = f >> 4, d4 = (f & 15) * 4;
            float4 v = *(const float4*)&A[(n0 + n) * XD + k0 + d4];
            xs[d4 + 0][n] = v.x;
            xs[d4 + 1][n] = v.y;
            xs[d4 + 2][n] = v.z;
            xs[d4 + 3][n] = v.w;
        }
#pragma unroll
        for (int r = 0; r < 4; r++) {
            int f = t + 256 * r;
            int d = f >> 4, h4 = (f & 15) * 4;
            *(float4*)&ws[d][h4] =
                *(const float4*)&W1[(z * XD + k0 + d) * HID + h0 + h4];
        }
        __syncthreads();
#pragma unroll 8
        for (int d = 0; d < 64; d++) {
            float4 a = *(const float4*)&ws[d][ty * 4];
            float4 b = *(const float4*)&xs[d][tx * 4];
            const float av[4] = {a.x, a.y, a.z, a.w};
            const float bv[4] = {b.x, b.y, b.z, b.w};
#pragma unroll
            for (int i = 0; i < 4; i++)
#pragma unroll
                for (int j = 0; j < 4; j++)
                    acc[i][j] = fmaf(av[i], bv[j], acc[i][j]);
        }
    }

#pragma unroll
    for (int i = 0; i < 4; i++) {
        int h = h0 + ty * 4 + i;
        float bias = z ? b1[h] : 0.f;
        float4 o = make_float4(acc[i][0] + bias, acc[i][1] + bias,
                               acc[i][2] + bias, acc[i][3] + bias);
        *(float4*)&C[h * NS + n0 + tx * 4] = o;
    }
}

// ---------------------------------------------------------------------------
// Pair kernel: block = 8 rows (i), all 1024 cols (j). 1024 threads
// (8 warps/SMSP): jp = t & 511 (j = 2jp, 2jp+1), i-half = t >> 9 (4 ii each).
// Thread owns 4i x 2j = 4 packed f32x2 accumulators. 4-deep LDG.64 prefetch.
// ---------------------------------------------------------------------------
__global__ __launch_bounds__(1024) void pair_kernel(
    const float* __restrict__ W2, const float* __restrict__ b2)
{
    __shared__ ull sm_py2[HID][8];    // dup'd pyb_T[k][ii] = {v,v}
    __shared__ ull sm_w2[HID];        // dup'd W2
    __shared__ float red_m[32][4];    // [warp][ii-local]
    __shared__ float red_s[32][4];

    const int t   = threadIdx.x;
    const int jp  = t & 511;          // j-pair index
    const int iib = (t >> 9) * 4;     // ii base: 0 or 4
    const int i0  = blockIdx.x * 8;

    // one-time: duplicate pyb columns + W2 into packed smem
#pragma unroll
    for (int r = 0; r < 2; r++) {
        int f = t + 1024 * r;         // 2048 entries
        int k = f >> 3, ii = f & 7;
        sm_py2[k][ii] = dup2(g_pybT[k * NS + i0 + ii]);
    }
    if (t < HID) sm_w2[t] = dup2(W2[t]);
    __syncthreads();

    ull acc2[4];
#pragma unroll
    for (int ii = 0; ii < 4; ii++) acc2[ii] = 0ull;

    const ull* pxu = (const ull*)g_pxT;   // row k: NS/2 = 512 packed pairs

    ull buf[2][4];
#pragma unroll
    for (int kk = 0; kk < 4; kk++)
        buf[0][kk] = pxu[kk * (NS / 2) + jp];

#pragma unroll 1
    for (int k0 = 0; k0 < HID; k0 += 4) {
        const int cur = (k0 >> 2) & 1, nxt = cur ^ 1;
        const int kn = (k0 + 4) & (HID - 1);   // wraps at end (harmless)
#pragma unroll
        for (int kk = 0; kk < 4; kk++)
            buf[nxt][kk] = pxu[(kn + kk) * (NS / 2) + jp];

#pragma unroll
        for (int kk = 0; kk < 4; kk++) {
            const ull w2v = sm_w2[k0 + kk];
            const ull p   = buf[cur][kk];
            ulonglong2 a01 = *(const ulonglong2*)&sm_py2[k0 + kk][iib];
            ulonglong2 a23 = *(const ulonglong2*)&sm_py2[k0 + kk][iib + 2];
            relu_fma2(acc2[0], a01.x, p, w2v);
            relu_fma2(acc2[1], a01.y, p, w2v);
            relu_fma2(acc2[2], a23.x, p, w2v);
            relu_fma2(acc2[3], a23.y, p, w2v);
        }
    }

    // epilogue: T1 = acc + b2 - 1 ; diagonal capture + per-i logsumexp
    const float bm1 = b2[0] - 1.0f;
    float m[4], s[4];
    union cvt { ull u; float2 f; };
#pragma unroll
    for (int ii = 0; ii < 4; ii++) {
        cvt c; c.u = acc2[ii];
        float v0 = c.f.x + bm1;
        float v1 = c.f.y + bm1;
        const int igl = i0 + iib + ii;
        if (2 * jp == igl)     g_diag[igl] = v0;
        if (2 * jp + 1 == igl) g_diag[igl] = v1;
        float mm = fmaxf(v0, v1);
        s[ii] = expf(v0 - mm) + expf(v1 - mm);
        m[ii] = mm;
    }

    // warp-level (m,s) merge
#pragma unroll
    for (int off = 16; off > 0; off >>= 1) {
#pragma unroll
        for (int ii = 0; ii < 4; ii++) {
            float om = __shfl_xor_sync(0xffffffffu, m[ii], off);
            float os = __shfl_xor_sync(0xffffffffu, s[ii], off);
            float M  = fmaxf(m[ii], om);
            s[ii] = s[ii] * expf(m[ii] - M) + os * expf(om - M);
            m[ii] = M;
        }
    }
    const int warp = t >> 5, lane = t & 31;
    if (lane == 0) {
#pragma unroll
        for (int ii = 0; ii < 4; ii++) {
            red_m[warp][ii] = m[ii];
            red_s[warp][ii] = s[ii];
        }
    }
    __syncthreads();
    if (t < 8) {
        // ii-global = t; warps 0-15 hold ii 0-3, warps 16-31 hold ii 4-7
        const int wbase = (t >> 2) * 16, col = t & 3;
        float M = red_m[wbase][col], S = red_s[wbase][col];
#pragma unroll
        for (int w = 1; w < 16; w++) {
            float om = red_m[wbase + w][col], os = red_s[wbase + w][col];
            float M2 = fmaxf(M, om);
            S = S * expf(M - M2) + os * expf(om - M2);
            M = M2;
        }
        float lse = M + logf(S);
        g_e[i0 + t] = expf(lse - logf((float)NS));
    }
}

// ---------------------------------------------------------------------------
// Final reduction: out = mean(diag) + 1 - mean(e)
// ---------------------------------------------------------------------------
__global__ __launch_bounds__(1024) void finish_kernel(float* __restrict__ out)
{
    __shared__ float sd[32];
    __shared__ float se[32];
    const int t = threadIdx.x;
    float d = g_diag[t];
    float e = g_e[t];
#pragma unroll
    for (int off = 16; off > 0; off >>= 1) {
        d += __shfl_xor_sync(0xffffffffu, d, off);
        e += __shfl_xor_sync(0xffffffffu, e, off);
    }
    const int warp = t >> 5, lane = t & 31;
    if (lane == 0) { sd[warp] = d; se[warp] = e; }
    __syncthreads();
    if (t < 32) {
        float dd = sd[t], ee = se[t];
#pragma unroll
        for (int off = 16; off > 0; off >>= 1) {
            dd += __shfl_xor_sync(0xffffffffu, dd, off);
            ee += __shfl_xor_sync(0xffffffffu, ee, off);
        }
        if (t == 0)
            out[0] = dd * (1.0f / NS) + 1.0f - ee * (1.0f / NS);
    }
}

// ---------------------------------------------------------------------------
extern "C" void kernel_launch(void* const* d_in, const int* in_sizes, int n_in,
                              void* d_out, int out_size)
{
    const float* x  = (const float*)d_in[0];
    const float* y  = (const float*)d_in[1];
    const float* W1 = (const float*)d_in[2];
    const float* b1 = (const float*)d_in[3];
    const float* W2 = (const float*)d_in[4];
    const float* b2 = (const float*)d_in[5];

    dim3 gg(NS / 64, HID / 64, 2);          // 16 x 4 x 2 = 128 blocks
    gemm_kernel<<<gg, 256>>>(x, y, W1, b1);
    pair_kernel<<<NS / 8, 1024>>>(W2, b2);  // 128 blocks, 8 warps/SMSP
    finish_kernel<<<1, 1024>>>((float*)d_out);
}

// round 7
// speedup vs baseline: 1.2796x; 1.2796x over previous
#include <cuda_runtime.h>
#include <math.h>

#define NS  1024
#define XD  128
#define HID 256

typedef unsigned long long ull;

// scratch (allocation-free rule: __device__ globals)
__device__ float g_pxT[HID * NS];   // [k][j] : px transposed
__device__ float g_pybT[HID * NS];  // [k][i] : (y@W1y + b1) transposed
__device__ float g_diag[NS];        // T1[i,i]
__device__ float g_e[NS];           // exp(lse_i - ln N)
__device__ int   g_ctr;             // last-block election (self-resetting)

// ---------------------------------------------------------------------------
// packed f32x2 helpers (sm_100+)
// ---------------------------------------------------------------------------
__device__ __forceinline__ ull dup2(float x) {
    ull r;
    asm("mov.b64 %0, {%1, %1};" : "=l"(r) : "f"(x));
    return r;
}

// acc2 += max(a2 + p2, 0) * w2   (elementwise on both packed lanes)
__device__ __forceinline__ void relu_fma2(ull& acc, ull a2, ull p2, ull w2) {
    asm("{\n\t"
        ".reg .b64 v;\n\t"
        ".reg .f32 lo, hi;\n\t"
        "add.rn.f32x2 v, %1, %2;\n\t"
        "mov.b64 {lo, hi}, v;\n\t"
        "max.f32 lo, lo, 0f00000000;\n\t"
        "max.f32 hi, hi, 0f00000000;\n\t"
        "mov.b64 v, {lo, hi};\n\t"
        "fma.rn.f32x2 %0, v, %3, %0;\n\t"
        "}"
        : "+l"(acc) : "l"(a2), "l"(p2), "l"(w2));
}

// ---------------------------------------------------------------------------
// GEMM: C_T[h][n] = sum_d A[n][d] * W1[z*128 + d][h]   (+ b1[h] when z==1)
// block tile 64h x 64n, 256 threads, thread tile 4h x 4n, smem-tiled,
// LDS.128 reads. (R5 config: measured 10.3us)
// ---------------------------------------------------------------------------
__global__ __launch_bounds__(256) void gemm_kernel(
    const float* __restrict__ X, const float* __restrict__ Y,
    const float* __restrict__ W1, const float* __restrict__ b1)
{
    const int z  = blockIdx.z;
    const float* A = z ? Y : X;
    float* C = z ? g_pybT : g_pxT;
    const int h0 = blockIdx.y * 64;
    const int n0 = blockIdx.x * 64;
    const int t  = threadIdx.x;
    const int tx = t & 15;   // n quad index
    const int ty = t >> 4;   // h quad index

    __shared__ float xs[64][68];  // [d][n] transposed, pad 68
    __shared__ float ws[64][64];  // [d][h]

    float acc[4][4];
#pragma unroll
    for (int i = 0; i < 4; i++)
#pragma unroll
        for (int j = 0; j < 4; j++) acc[i][j] = 0.f;

    for (int k0 = 0; k0 < XD; k0 += 64) {
        __syncthreads();
#pragma unroll
        for (int r = 0; r < 4; r++) {
            int f = t + 256 * r;          // 1024 float4s
            int n = f >> 4, d4 = (f & 15) * 4;
            float4 v = *(const float4*)&A[(n0 + n) * XD + k0 + d4];
            xs[d4 + 0][n] = v.x;
            xs[d4 + 1][n] = v.y;
            xs[d4 + 2][n] = v.z;
            xs[d4 + 3][n] = v.w;
        }
#pragma unroll
        for (int r = 0; r < 4; r++) {
            int f = t + 256 * r;
            int d = f >> 4, h4 = (f & 15) * 4;
            *(float4*)&ws[d][h4] =
                *(const float4*)&W1[(z * XD + k0 + d) * HID + h0 + h4];
        }
        __syncthreads();
#pragma unroll 8
        for (int d = 0; d < 64; d++) {
            float4 a = *(const float4*)&ws[d][ty * 4];
            float4 b = *(const float4*)&xs[d][tx * 4];
            const float av[4] = {a.x, a.y, a.z, a.w};
            const float bv[4] = {b.x, b.y, b.z, b.w};
#pragma unroll
            for (int i = 0; i < 4; i++)
#pragma unroll
                for (int j = 0; j < 4; j++)
                    acc[i][j] = fmaf(av[i], bv[j], acc[i][j]);
        }
    }

#pragma unroll
    for (int i = 0; i < 4; i++) {
        int h = h0 + ty * 4 + i;
        float bias = z ? b1[h] : 0.f;
        float4 o = make_float4(acc[i][0] + bias, acc[i][1] + bias,
                               acc[i][2] + bias, acc[i][3] + bias);
        *(float4*)&C[h * NS + n0 + tx * 4] = o;
    }
}

// ---------------------------------------------------------------------------
// Pair kernel (R4 config: measured 26us): block = 8 rows (i), all 1024 cols
// (j). 512 threads, thread owns 8i x 2j (8 packed f32x2 accumulators).
// Unique jp per thread, LDG.64 px, broadcast LDS for dup'd py/w2, 4-deep
// double-buffered prefetch. Last block also performs the final reduction.
// ---------------------------------------------------------------------------
__global__ __launch_bounds__(512) void pair_kernel(
    const float* __restrict__ W2, const float* __restrict__ b2,
    float* __restrict__ out)
{
    __shared__ ull sm_py2[HID][8];    // dup'd pyb_T[k][ii] = {v,v}
    __shared__ ull sm_w2[HID];        // dup'd W2
    __shared__ float red_m[16][8];    // [warp][ii]
    __shared__ float red_s[16][8];

    const int t  = threadIdx.x;       // j-pair index: j = 2t, 2t+1
    const int i0 = blockIdx.x * 8;

    // one-time: duplicate pyb columns + W2 into packed smem
#pragma unroll
    for (int r = 0; r < 4; r++) {
        int f = t + 512 * r;          // 2048 entries
        int k = f >> 3, ii = f & 7;
        sm_py2[k][ii] = dup2(g_pybT[k * NS + i0 + ii]);
    }
    if (t < HID) sm_w2[t] = dup2(W2[t]);
    __syncthreads();

    ull acc2[8];
#pragma unroll
    for (int ii = 0; ii < 8; ii++) acc2[ii] = 0ull;

    // px rows as packed j-pairs: row k = 512 ull
    const ull* pxu = (const ull*)g_pxT;

    ull buf[2][4];
#pragma unroll
    for (int kk = 0; kk < 4; kk++)
        buf[0][kk] = pxu[kk * (NS / 2) + t];

#pragma unroll 1
    for (int k0 = 0; k0 < HID; k0 += 4) {
        const int cur = (k0 >> 2) & 1, nxt = cur ^ 1;
        const int kn = (k0 + 4) & (HID - 1);   // wraps at end (harmless)
#pragma unroll
        for (int kk = 0; kk < 4; kk++)
            buf[nxt][kk] = pxu[(kn + kk) * (NS / 2) + t];

#pragma unroll
        for (int kk = 0; kk < 4; kk++) {
            const ull w2v = sm_w2[k0 + kk];
            const ull p   = buf[cur][kk];
            ulonglong2 a01 = *(const ulonglong2*)&sm_py2[k0 + kk][0];
            ulonglong2 a23 = *(const ulonglong2*)&sm_py2[k0 + kk][2];
            ulonglong2 a45 = *(const ulonglong2*)&sm_py2[k0 + kk][4];
            ulonglong2 a67 = *(const ulonglong2*)&sm_py2[k0 + kk][6];
            relu_fma2(acc2[0], a01.x, p, w2v);
            relu_fma2(acc2[1], a01.y, p, w2v);
            relu_fma2(acc2[2], a23.x, p, w2v);
            relu_fma2(acc2[3], a23.y, p, w2v);
            relu_fma2(acc2[4], a45.x, p, w2v);
            relu_fma2(acc2[5], a45.y, p, w2v);
            relu_fma2(acc2[6], a67.x, p, w2v);
            relu_fma2(acc2[7], a67.y, p, w2v);
        }
    }

    // epilogue: T1 = acc + b2 - 1 ; diagonal capture + per-i logsumexp
    const float bm1 = b2[0] - 1.0f;
    float m[8], s[8];
    union cvt { ull u; float2 f; };
#pragma unroll
    for (int ii = 0; ii < 8; ii++) {
        cvt c; c.u = acc2[ii];
        float v0 = c.f.x + bm1;
        float v1 = c.f.y + bm1;
        const int ig = i0 + ii;
        if (2 * t == ig)     g_diag[ig] = v0;
        if (2 * t + 1 == ig) g_diag[ig] = v1;
        float mm = fmaxf(v0, v1);
        s[ii] = expf(v0 - mm) + expf(v1 - mm);
        m[ii] = mm;
    }

    // warp-level (m,s) merge
#pragma unroll
    for (int off = 16; off > 0; off >>= 1) {
#pragma unroll
        for (int ii = 0; ii < 8; ii++) {
            float om = __shfl_xor_sync(0xffffffffu, m[ii], off);
            float os = __shfl_xor_sync(0xffffffffu, s[ii], off);
            float M  = fmaxf(m[ii], om);
            s[ii] = s[ii] * expf(m[ii] - M) + os * expf(om - M);
            m[ii] = M;
        }
    }
    const int warp = t >> 5, lane = t & 31;
    if (lane == 0) {
#pragma unroll
        for (int ii = 0; ii < 8; ii++) {
            red_m[warp][ii] = m[ii];
            red_s[warp][ii] = s[ii];
        }
    }
    __syncthreads();
    if (t < 8) {
        float M = red_m[0][t], S = red_s[0][t];
#pragma unroll
        for (int w = 1; w < 16; w++) {
            float om = red_m[w][t], os = red_s[w][t];
            float M2 = fmaxf(M, om);
            S = S * expf(M - M2) + os * expf(om - M2);
            M = M2;
        }
        float lse = M + logf(S);
        g_e[i0 + t] = expf(lse - logf((float)NS));
    }

    // ---- fused finish: last block reduces diag + e and writes the scalar ----
    __syncthreads();
    __shared__ int s_last;
    if (t == 0) {
        __threadfence();
        s_last = (atomicAdd(&g_ctr, 1) == gridDim.x - 1);
    }
    __syncthreads();
    if (!s_last) return;

    __shared__ float sd[16], se[16];
    float d = g_diag[t] + g_diag[t + 512];
    float e = g_e[t]    + g_e[t + 512];
#pragma unroll
    for (int off = 16; off > 0; off >>= 1) {
        d += __shfl_xor_sync(0xffffffffu, d, off);
        e += __shfl_xor_sync(0xffffffffu, e, off);
    }
    if (lane == 0) { sd[warp] = d; se[warp] = e; }
    __syncthreads();
    if (t < 16) {
        float dd = sd[t], ee = se[t];
#pragma unroll
        for (int off = 8; off > 0; off >>= 1) {
            dd += __shfl_xor_sync(0xffffu, dd, off);
            ee += __shfl_xor_sync(0xffffu, ee, off);
        }
        if (t == 0) {
            out[0] = dd * (1.0f / NS) + 1.0f - ee * (1.0f / NS);
            g_ctr = 0;                       // self-reset for graph replay
        }
    }
}

// ---------------------------------------------------------------------------
extern "C" void kernel_launch(void* const* d_in, const int* in_sizes, int n_in,
                              void* d_out, int out_size)
{
    const float* x  = (const float*)d_in[0];
    const float* y  = (const float*)d_in[1];
    const float* W1 = (const float*)d_in[2];
    const float* b1 = (const float*)d_in[3];
    const float* W2 = (const float*)d_in[4];
    const float* b2 = (const float*)d_in[5];

    dim3 gg(NS / 64, HID / 64, 2);          // 16 x 4 x 2 = 128 blocks
    gemm_kernel<<<gg, 256>>>(x, y, W1, b1);
    pair_kernel<<<NS / 8, 512>>>(W2, b2, (float*)d_out);  // 128 blocks
}

// round 8
// speedup vs baseline: 1.2867x; 1.0055x over previous
#include <cuda_runtime.h>
#include <math.h>

#define NS  1024
#define XD  128
#define HID 256

typedef unsigned long long ull;

// scratch (allocation-free rule: __device__ globals)
__device__ float g_pxT[HID * NS];   // [k][j] : px transposed
__device__ float g_pybT[HID * NS];  // [k][i] : (y@W1y + b1) transposed
__device__ float g_diag[NS];        // T1[i,i]
__device__ float g_e[NS];           // exp(lse_i - ln N)
__device__ int   g_ctr;             // last-block election (self-resetting)

// ---------------------------------------------------------------------------
// packed f32x2 helpers (sm_100+)
// ---------------------------------------------------------------------------
__device__ __forceinline__ ull dup2(float x) {
    ull r;
    asm("mov.b64 %0, {%1, %1};" : "=l"(r) : "f"(x));
    return r;
}

// acc2 += max(a2 + p2, 0) * w2   (elementwise on both packed lanes)
__device__ __forceinline__ void relu_fma2(ull& acc, ull a2, ull p2, ull w2) {
    asm("{\n\t"
        ".reg .b64 v;\n\t"
        ".reg .f32 lo, hi;\n\t"
        "add.rn.f32x2 v, %1, %2;\n\t"
        "mov.b64 {lo, hi}, v;\n\t"
        "max.f32 lo, lo, 0f00000000;\n\t"
        "max.f32 hi, hi, 0f00000000;\n\t"
        "mov.b64 v, {lo, hi};\n\t"
        "fma.rn.f32x2 %0, v, %3, %0;\n\t"
        "}"
        : "+l"(acc) : "l"(a2), "l"(p2), "l"(w2));
}

// ---------------------------------------------------------------------------
// GEMM: C_T[h][n] = sum_d A[n][d] * W1[z*128 + d][h]   (+ b1[h] when z==1)
// block tile 64h x 64n, 512 threads (4 warps/SMSP), thread tile 2h x 4n,
// smem-tiled both operands.
// ---------------------------------------------------------------------------
__global__ __launch_bounds__(512) void gemm_kernel(
    const float* __restrict__ X, const float* __restrict__ Y,
    const float* __restrict__ W1, const float* __restrict__ b1)
{
    const int z  = blockIdx.z;
    const float* A = z ? Y : X;
    float* C = z ? g_pybT : g_pxT;
    const int h0 = blockIdx.y * 64;
    const int n0 = blockIdx.x * 64;
    const int t  = threadIdx.x;
    const int tx = t & 15;   // n quad index
    const int ty = t >> 4;   // h pair index (0..31)

    __shared__ float xs[64][68];  // [d][n] transposed, pad 68 (rows 16B-aligned)
    __shared__ float ws[64][64];  // [d][h]

    float acc[2][4];
#pragma unroll
    for (int i = 0; i < 2; i++)
#pragma unroll
        for (int j = 0; j < 4; j++) acc[i][j] = 0.f;

    for (int k0 = 0; k0 < XD; k0 += 64) {
        __syncthreads();
#pragma unroll
        for (int r = 0; r < 2; r++) {
            int f = t + 512 * r;          // 1024 float4s
            int n = f >> 4, d4 = (f & 15) * 4;
            float4 v = *(const float4*)&A[(n0 + n) * XD + k0 + d4];
            xs[d4 + 0][n] = v.x;
            xs[d4 + 1][n] = v.y;
            xs[d4 + 2][n] = v.z;
            xs[d4 + 3][n] = v.w;
        }
#pragma unroll
        for (int r = 0; r < 2; r++) {
            int f = t + 512 * r;
            int d = f >> 4, h4 = (f & 15) * 4;
            *(float4*)&ws[d][h4] =
                *(const float4*)&W1[(z * XD + k0 + d) * HID + h0 + h4];
        }
        __syncthreads();
#pragma unroll 8
        for (int d = 0; d < 64; d++) {
            float2 a = *(const float2*)&ws[d][ty * 2];
            float4 b = *(const float4*)&xs[d][tx * 4];
            const float av[2] = {a.x, a.y};
            const float bv[4] = {b.x, b.y, b.z, b.w};
#pragma unroll
            for (int i = 0; i < 2; i++)
#pragma unroll
                for (int j = 0; j < 4; j++)
                    acc[i][j] = fmaf(av[i], bv[j], acc[i][j]);
        }
    }

#pragma unroll
    for (int i = 0; i < 2; i++) {
        int h = h0 + ty * 2 + i;
        float bias = z ? b1[h] : 0.f;
        float4 o = make_float4(acc[i][0] + bias, acc[i][1] + bias,
                               acc[i][2] + bias, acc[i][3] + bias);
        *(float4*)&C[h * NS + n0 + tx * 4] = o;
    }
}

// ---------------------------------------------------------------------------
// Pair kernel with K-SPLIT: block = 8 rows (i) x 1024 cols (j), 1024 threads.
// Group g = t>>9 reduces k in [g*128, g*128+128) for jp = t&511
// (8i x 2j accumulators each). No px LDG duplication; 8 warps/SMSP.
// Partials merged through reused smem; group 0 finishes lse; last block
// does the final scalar reduction.
// ---------------------------------------------------------------------------
__global__ __launch_bounds__(1024) void pair_kernel(
    const float* __restrict__ W2, const float* __restrict__ b2,
    float* __restrict__ out)
{
    __shared__ ull sm_py2[HID][8];    // dup'd pyb_T[k][ii] = {v,v} (16KB)
    __shared__ ull sm_w2[HID];        // dup'd W2 (2KB)
    __shared__ float red_m[16][8];    // [grp0 warp][ii]
    __shared__ float red_s[16][8];
    __shared__ int   s_last;
    __shared__ float sd[32], se[32];

    const int t   = threadIdx.x;
    const int jp  = t & 511;          // j-pair index: j = 2jp, 2jp+1
    const int grp = t >> 9;           // k half
    const int i0  = blockIdx.x * 8;

    // one-time: duplicate pyb columns + W2 into packed smem
#pragma unroll
    for (int r = 0; r < 2; r++) {
        int f = t + 1024 * r;         // 2048 entries
        int k = f >> 3, ii = f & 7;
        sm_py2[k][ii] = dup2(g_pybT[k * NS + i0 + ii]);
    }
    if (t < HID) sm_w2[t] = dup2(W2[t]);
    __syncthreads();

    ull acc2[8];
#pragma unroll
    for (int ii = 0; ii < 8; ii++) acc2[ii] = 0ull;

    const int kb = grp * (HID / 2);       // this group's k base
    const ull* pxu = (const ull*)g_pxT;   // row k: NS/2 = 512 packed pairs

    ull buf[2][4];
#pragma unroll
    for (int kk = 0; kk < 4; kk++)
        buf[0][kk] = pxu[(kb + kk) * (NS / 2) + jp];

#pragma unroll 1
    for (int kl = 0; kl < HID / 2; kl += 4) {
        const int cur = (kl >> 2) & 1, nxt = cur ^ 1;
        const int knl = (kl + 4) & (HID / 2 - 1);   // wraps at end (harmless)
#pragma unroll
        for (int kk = 0; kk < 4; kk++)
            buf[nxt][kk] = pxu[(kb + knl + kk) * (NS / 2) + jp];

#pragma unroll
        for (int kk = 0; kk < 4; kk++) {
            const int k = kb + kl + kk;
            const ull w2v = sm_w2[k];
            const ull p   = buf[cur][kk];
            ulonglong2 a01 = *(const ulonglong2*)&sm_py2[k][0];
            ulonglong2 a23 = *(const ulonglong2*)&sm_py2[k][2];
            ulonglong2 a45 = *(const ulonglong2*)&sm_py2[k][4];
            ulonglong2 a67 = *(const ulonglong2*)&sm_py2[k][6];
            relu_fma2(acc2[0], a01.x, p, w2v);
            relu_fma2(acc2[1], a01.y, p, w2v);
            relu_fma2(acc2[2], a23.x, p, w2v);
            relu_fma2(acc2[3], a23.y, p, w2v);
            relu_fma2(acc2[4], a45.x, p, w2v);
            relu_fma2(acc2[5], a45.y, p, w2v);
            relu_fma2(acc2[6], a67.x, p, w2v);
            relu_fma2(acc2[7], a67.y, p, w2v);
        }
    }

    // ---- merge k-halves: reuse sm_py2 (16KB) as exchange, 2 rounds of 4 ----
    ull (*xch)[512] = (ull(*)[512])sm_py2;   // [4][512]
    union cvt { ull u; float2 f; };
    __syncthreads();                  // main loop done; sm_py2 reusable
    if (grp == 1) {
#pragma unroll
        for (int ii = 0; ii < 4; ii++) xch[ii][jp] = acc2[ii];
    }
    __syncthreads();
    if (grp == 0) {
#pragma unroll
        for (int ii = 0; ii < 4; ii++) {
            cvt a, b; a.u = acc2[ii]; b.u = xch[ii][jp];
            a.f.x += b.f.x; a.f.y += b.f.y; acc2[ii] = a.u;
        }
    }
    __syncthreads();
    if (grp == 1) {
#pragma unroll
        for (int ii = 0; ii < 4; ii++) xch[ii][jp] = acc2[ii + 4];
    }
    __syncthreads();
    if (grp == 0) {
#pragma unroll
        for (int ii = 0; ii < 4; ii++) {
            cvt a, b; a.u = acc2[ii + 4]; b.u = xch[ii][jp];
            a.f.x += b.f.x; a.f.y += b.f.y; acc2[ii + 4] = a.u;
        }
    }

    const int warp = t >> 5, lane = t & 31;

    // ---- epilogue (group 0 only; warp-uniform branch) ----
    if (grp == 0) {
        const float bm1 = b2[0] - 1.0f;
        float m[8], s[8];
#pragma unroll
        for (int ii = 0; ii < 8; ii++) {
            cvt c; c.u = acc2[ii];
            float v0 = c.f.x + bm1;
            float v1 = c.f.y + bm1;
            const int ig = i0 + ii;
            if (2 * jp == ig)     g_diag[ig] = v0;
            if (2 * jp + 1 == ig) g_diag[ig] = v1;
            float mm = fmaxf(v0, v1);
            s[ii] = expf(v0 - mm) + expf(v1 - mm);
            m[ii] = mm;
        }
#pragma unroll
        for (int off = 16; off > 0; off >>= 1) {
#pragma unroll
            for (int ii = 0; ii < 8; ii++) {
                float om = __shfl_xor_sync(0xffffffffu, m[ii], off);
                float os = __shfl_xor_sync(0xffffffffu, s[ii], off);
                float M  = fmaxf(m[ii], om);
                s[ii] = s[ii] * expf(m[ii] - M) + os * expf(om - M);
                m[ii] = M;
            }
        }
        if (lane == 0) {
#pragma unroll
            for (int ii = 0; ii < 8; ii++) {
                red_m[warp][ii] = m[ii];
                red_s[warp][ii] = s[ii];
            }
        }
    }
    __syncthreads();
    if (t < 8) {
        float M = red_m[0][t], S = red_s[0][t];
#pragma unroll
        for (int w = 1; w < 16; w++) {
            float om = red_m[w][t], os = red_s[w][t];
            float M2 = fmaxf(M, om);
            S = S * expf(M - M2) + os * expf(om - M2);
            M = M2;
        }
        float lse = M + logf(S);
        g_e[i0 + t] = expf(lse - logf((float)NS));
    }

    // ---- fused finish: last block reduces diag + e, writes the scalar ----
    __threadfence();
    __syncthreads();
    if (t == 0)
        s_last = (atomicAdd(&g_ctr, 1) == (int)gridDim.x - 1);
    __syncthreads();
    if (!s_last) return;
    __threadfence();                  // acquire other blocks' writes

    float d = g_diag[t];
    float e = g_e[t];
#pragma unroll
    for (int off = 16; off > 0; off >>= 1) {
        d += __shfl_xor_sync(0xffffffffu, d, off);
        e += __shfl_xor_sync(0xffffffffu, e, off);
    }
    if (lane == 0) { sd[warp] = d; se[warp] = e; }
    __syncthreads();
    if (t < 32) {
        float dd = sd[t], ee = se[t];
#pragma unroll
        for (int off = 16; off > 0; off >>= 1) {
            dd += __shfl_xor_sync(0xffffffffu, dd, off);
            ee += __shfl_xor_sync(0xffffffffu, ee, off);
        }
        if (t == 0) {
            out[0] = dd * (1.0f / NS) + 1.0f - ee * (1.0f / NS);
            g_ctr = 0;                // self-reset for graph replay
        }
    }
}

// ---------------------------------------------------------------------------
extern "C" void kernel_launch(void* const* d_in, const int* in_sizes, int n_in,
                              void* d_out, int out_size)
{
    const float* x  = (const float*)d_in[0];
    const float* y  = (const float*)d_in[1];
    const float* W1 = (const float*)d_in[2];
    const float* b1 = (const float*)d_in[3];
    const float* W2 = (const float*)d_in[4];
    const float* b2 = (const float*)d_in[5];

    dim3 gg(NS / 64, HID / 64, 2);          // 16 x 4 x 2 = 128 blocks
    gemm_kernel<<<gg, 512>>>(x, y, W1, b1);
    pair_kernel<<<NS / 8, 1024>>>(W2, b2, (float*)d_out);  // 128 blocks
}